// round 4
// baseline (speedup 1.0000x reference)
#include <cuda_runtime.h>
#include <cstdint>

#define K_VOL 27
#define HALFK 1
#define SENC 258
#define NK_MAX 2700000
#define TAB_BITS 23
#define TAB (1u << TAB_BITS)
#define TMASK (TAB - 1u)
#define SCAN_ELEMS 4096                // per block (256 thr x 16)
#define NBLK_SCAN_MAX 1024

__device__ int g_ht_key[TAB];          // -1 = empty
__device__ int g_ht_val[TAB];          // min flat index per key
__device__ int g_slot[NK_MAX];         // hash slot -> then min flat index
__device__ int g_scan[NK_MAX];         // inclusive scan of winner flags
__device__ unsigned g_blkctr;
__device__ unsigned long long g_state[NBLK_SCAN_MAX]; // (status<<32)|value

// 1) clear hash table + scan state
__global__ void k_init() {
    unsigned i = blockIdx.x * blockDim.x + threadIdx.x;
    if (i * 4 < TAB) {
        ((int4*)g_ht_key)[i] = make_int4(-1, -1, -1, -1);
        ((int4*)g_ht_val)[i] = make_int4(0x7fffffff, 0x7fffffff, 0x7fffffff, 0x7fffffff);
    }
    if (i < NBLK_SCAN_MAX) g_state[i] = 0ULL;
    if (i == 0) g_blkctr = 0u;
}

// 2) encode + hash insert + atomicMin of flat index
__global__ void k_build(const int* __restrict__ si, int N, int NK) {
    int i = blockIdx.x * blockDim.x + threadIdx.x;
    if (i >= NK) return;
    int n = i / K_VOL;
    int k = i - n * K_VOL;
    int b = si[n];
    int x = si[N + n]     + (k / 9);
    int y = si[2 * N + n] + ((k / 3) % 3);
    int z = si[3 * N + n] + (k % 3);
    int enc = ((b * SENC + x) * SENC + y) * SENC + z;

    unsigned h = ((unsigned)enc * 2654435761u) >> (32 - TAB_BITS);
    for (;;) {
        int cur = g_ht_key[h];
        if (cur == enc) break;
        if (cur == -1) {
            cur = atomicCAS(&g_ht_key[h], -1, enc);
            if (cur == -1 || cur == enc) break;
        }
        h = (h + 1) & TMASK;
    }
    atomicMin(&g_ht_val[h], i);
    g_slot[i] = (int)h;
}

// 3) fused: resolve min index, winner flag, single-pass decoupled-lookback scan
__global__ void k_scan(int NK) {
    __shared__ int s_data[SCAN_ELEMS];
    __shared__ int s_warp[8];
    __shared__ unsigned s_blk;
    __shared__ int s_excl;

    int t = threadIdx.x;
    if (t == 0) s_blk = atomicAdd(&g_blkctr, 1u);
    __syncthreads();
    unsigned blk = s_blk;
    int base = (int)blk * SCAN_ELEMS;

    // coalesced load + ht_val resolve (16-deep MLP), stage m into shared
#pragma unroll
    for (int j = 0; j < 16; j++) {
        int idx = base + j * 256 + t;
        int m = 0x7fffffff;
        if (idx < NK) {
            int s = g_slot[idx];
            m = g_ht_val[s];
            g_slot[idx] = m;               // overwrite slot with min index
        }
        s_data[j * 256 + t] = m;
    }
    __syncthreads();

    // per-thread serial scan over its contiguous 16
    int v[16];
    int run = 0;
#pragma unroll
    for (int j = 0; j < 16; j++) {
        int l = t * 16 + j;
        int f = (s_data[l] == base + l) ? 1 : 0;
        run += f;
        v[j] = run;
    }

    // warp + block scan of per-thread sums
    int lane = t & 31, wid = t >> 5;
    int inc = run;
#pragma unroll
    for (int off = 1; off < 32; off <<= 1) {
        int y = __shfl_up_sync(0xffffffffu, inc, off);
        if (lane >= off) inc += y;
    }
    if (lane == 31) s_warp[wid] = inc;
    __syncthreads();
    if (t < 8) {
        int w = s_warp[t];
#pragma unroll
        for (int off = 1; off < 8; off <<= 1) {
            int y = __shfl_up_sync(0xffu, w, off);
            if ((int)t >= off) w += y;
        }
        s_warp[t] = w;                      // inclusive
    }
    __syncthreads();
    int total = s_warp[7];
    int thr_excl = (inc - run) + (wid ? s_warp[wid - 1] : 0);

    // decoupled lookback (thread 0)
    if (t == 0) {
        if (blk == 0) {
            atomicExch(&g_state[0], (2ULL << 32) | (unsigned)total);
            s_excl = 0;
        } else {
            atomicExch(&g_state[blk], (1ULL << 32) | (unsigned)total);
            int excl = 0;
            int j = (int)blk - 1;
            for (;;) {
                unsigned long long st;
                do { st = atomicAdd(&g_state[j], 0ULL); } while ((st >> 32) == 0ULL);
                excl += (int)(unsigned)st;
                if ((st >> 32) == 2ULL) break;
                j--;
            }
            atomicExch(&g_state[blk], (2ULL << 32) | (unsigned)(excl + total));
            s_excl = excl;
        }
    }
    __syncthreads();
    int bexcl = s_excl;

    // stage final inclusive values, write coalesced
#pragma unroll
    for (int j = 0; j < 16; j++) s_data[t * 16 + j] = v[j] + thr_excl + bexcl;
    __syncthreads();
#pragma unroll
    for (int j = 0; j < 16; j++) {
        int idx = base + j * 256 + t;
        if (idx < NK) g_scan[idx] = s_data[j * 256 + t];
    }
}

// 4) fused output: kernel_map, out_key, winner features, tail fill. 8 lanes/row.
__global__ void k_out(int N, int NK, const int* __restrict__ si,
                      const float4* __restrict__ feat,
                      float* __restrict__ km, float* __restrict__ ok,
                      float4* __restrict__ outf) {
    long long tid = (long long)blockIdx.x * blockDim.x + threadIdx.x;
    int i = (int)(tid >> 3);
    int lane = (int)(tid & 7);
    if (i >= NK) return;

    int m = g_slot[i];
    int u = g_scan[m] - 1;
    int n = i / K_VOL;
    int k = i - n * K_VOL;

    if (lane == 0) {
        km[(size_t)3 * i]     = (float)n;
        km[(size_t)3 * i + 1] = (float)u;
        km[(size_t)3 * i + 2] = (float)k;
    }
    if (m == i) {
        if (lane == 1) {
            int x = si[N + n]     + (k / 9)       - HALFK;
            int y = si[2 * N + n] + ((k / 3) % 3) - HALFK;
            int z = si[3 * N + n] + (k % 3)       - HALFK;
            ok[(size_t)3 * u]     = (float)x;
            ok[(size_t)3 * u + 1] = (float)y;
            ok[(size_t)3 * u + 2] = (float)z;
        }
        outf[(size_t)u * 8 + lane] = feat[(size_t)n * 8 + lane];
    }
    // tail fill of output row i (rows >= U get -1 / 0)
    int U = g_scan[NK - 1];
    if (i >= U) {
        if (lane == 1) {
            ok[(size_t)3 * i]     = -1.0f;
            ok[(size_t)3 * i + 1] = -1.0f;
            ok[(size_t)3 * i + 2] = -1.0f;
        }
        outf[(size_t)i * 8 + lane] = make_float4(0.f, 0.f, 0.f, 0.f);
    }
}

// 5) duplicates: atomicAdd into winner rows (ordered after k_out)
__global__ void k_featd(int NK, const float* __restrict__ feat, float* __restrict__ outf) {
    int i = blockIdx.x * blockDim.x + threadIdx.x;
    if (i >= NK) return;
    int m = g_slot[i];
    if (m == i) return;
    int u = g_scan[m] - 1;
    int n = i / K_VOL;
    const float* src = feat + (size_t)n * 32;
    float* dst = outf + (size_t)u * 32;
#pragma unroll
    for (int c = 0; c < 32; c++) atomicAdd(dst + c, src[c]);
}

extern "C" void kernel_launch(void* const* d_in, const int* in_sizes, int n_in,
                              void* d_out, int out_size) {
    const int* si = (const int*)d_in[0];
    const float* feat = (const float*)d_in[1];
    int N = in_sizes[0] / 4;
    int NK = N * K_VOL;

    float* out = (float*)d_out;
    float* out_km = out;
    float* out_ok = out + (size_t)3 * NK;
    float* out_of = out + (size_t)6 * NK;

    const int T = 256;
    int gNK = (NK + T - 1) / T;
    int nblk = (NK + SCAN_ELEMS - 1) / SCAN_ELEMS;

    k_init<<<(TAB / 4 + T - 1) / T, T>>>();
    k_build<<<gNK, T>>>(si, N, NK);
    k_scan<<<nblk, T>>>(NK);
    {
        long long lanes = (long long)NK * 8;
        int g = (int)((lanes + T - 1) / T);
        k_out<<<g, T>>>(N, NK, si, (const float4*)feat, out_km, out_ok, (float4*)out_of);
    }
    k_featd<<<gNK, T>>>(NK, feat, out_of);
}

// round 5
// speedup vs baseline: 1.0076x; 1.0076x over previous
#include <cuda_runtime.h>
#include <cstdint>

#define K_VOL 27
#define HALFK 1
#define SENC 258
#define NK_MAX 2700000
#define TAB_BITS 23
#define TAB (1u << TAB_BITS)
#define TMASK (TAB - 1u)
#define SCAN_ELEMS 4096                // 256 threads x 16
#define NBLK_SCAN_MAX 1022

// aux layout: [0]=block ticket, [1]=dup count, [2..]=lookback states
#define AUX_TICKET 0
#define AUX_DUP    1
#define AUX_STATE  2

__device__ int g_ht_key[TAB];          // -1 = empty
__device__ int g_ht_val[TAB];          // min flat index per key (init 0x7f7f7f7f)
__device__ int g_slot[NK_MAX];         // hash slot -> then min flat index
__device__ int g_scan[NK_MAX];         // inclusive scan of winner flags
__device__ int g_dup[NK_MAX];          // compacted duplicate entry indices
__device__ unsigned long long g_aux[NBLK_SCAN_MAX + 2];

// 1) encode + hash insert + atomicMin of flat index
__global__ __launch_bounds__(256) void k_build(const int* __restrict__ si, int N, int NK) {
    int i = blockIdx.x * blockDim.x + threadIdx.x;
    if (i >= NK) return;
    int n = i / K_VOL;
    int k = i - n * K_VOL;
    int b = si[n];
    int x = si[N + n]     + (k / 9);
    int y = si[2 * N + n] + ((k / 3) % 3);
    int z = si[3 * N + n] + (k % 3);
    int enc = ((b * SENC + x) * SENC + y) * SENC + z;

    unsigned h = ((unsigned)enc * 2654435761u) >> (32 - TAB_BITS);
    for (;;) {
        int cur = g_ht_key[h];
        if (cur == enc) break;
        if (cur == -1) {
            cur = atomicCAS(&g_ht_key[h], -1, enc);
            if (cur == -1 || cur == enc) break;
        }
        h = (h + 1) & TMASK;
    }
    atomicMin(&g_ht_val[h], i);
    g_slot[i] = (int)h;
}

// 2) fused: resolve min index, decoupled-lookback scan, km+ok emission (staged
//    in shared for coalesced stores), duplicate compaction.
__global__ __launch_bounds__(256) void k_scan(int NK, const int* __restrict__ si, int N,
                                              float* __restrict__ km, float* __restrict__ ok) {
    __shared__ alignas(16) float s_buf[12288];   // 48KB staging (aliased as int)
    __shared__ int s_warp[8];
    __shared__ unsigned s_blk;
    __shared__ int s_excl;
    int* s_int = (int*)s_buf;

    int t = threadIdx.x;
    if (t == 0) s_blk = (unsigned)atomicAdd(&g_aux[AUX_TICKET], 1ULL);
    __syncthreads();
    int blk = (int)s_blk;
    int base = blk * SCAN_ELEMS;

    // --- load + resolve min index (coalesced, 16-deep MLP) ---
#pragma unroll
    for (int j = 0; j < 16; j++) {
        int idx = base + j * 256 + t;
        int m = -1;
        if (idx < NK) {
            int s = g_slot[idx];
            m = g_ht_val[s];
            g_slot[idx] = m;
        }
        s_int[j * 256 + t] = m;
    }
    __syncthreads();

    // --- per-thread serial scan over contiguous 16 ---
    int v[16];
    unsigned fmask = 0;
    int run = 0;
#pragma unroll
    for (int j = 0; j < 16; j++) {
        int l = t * 16 + j;
        int f = (s_int[l] == base + l) ? 1 : 0;
        fmask |= (unsigned)f << j;
        run += f;
        v[j] = run;
    }
    __syncthreads();   // done reading s_int

    // --- warp + block scan of per-thread sums ---
    int lane = t & 31, wid = t >> 5;
    int inc = run;
#pragma unroll
    for (int off = 1; off < 32; off <<= 1) {
        int y = __shfl_up_sync(0xffffffffu, inc, off);
        if (lane >= off) inc += y;
    }
    if (lane == 31) s_warp[wid] = inc;
    __syncthreads();
    if (t < 8) {
        int w = s_warp[t];
#pragma unroll
        for (int off = 1; off < 8; off <<= 1) {
            int y = __shfl_up_sync(0xffu, w, off);
            if ((int)t >= off) w += y;
        }
        s_warp[t] = w;
    }
    __syncthreads();
    int total = s_warp[7];
    int thr_excl = (inc - run) + (wid ? s_warp[wid - 1] : 0);

    // --- decoupled lookback ---
    if (t == 0) {
        unsigned long long* st = &g_aux[AUX_STATE];
        if (blk == 0) {
            atomicExch(&st[0], (2ULL << 32) | (unsigned)total);
            s_excl = 0;
        } else {
            atomicExch(&st[blk], (1ULL << 32) | (unsigned)total);
            int excl = 0;
            int j = blk - 1;
            for (;;) {
                unsigned long long s;
                do { s = atomicAdd(&st[j], 0ULL); } while ((s >> 32) == 0ULL);
                excl += (int)(unsigned)s;
                if ((s >> 32) == 2ULL) break;
                j--;
            }
            atomicExch(&st[blk], (2ULL << 32) | (unsigned)(excl + total));
            s_excl = excl;
        }
    }
    __syncthreads();
    int bexcl = s_excl;
    int nelem = NK - base; if (nelem > SCAN_ELEMS) nelem = SCAN_ELEMS;

    // --- stage + store inclusive scan (coalesced) ---
#pragma unroll
    for (int j = 0; j < 16; j++) s_int[t * 16 + j] = v[j] + thr_excl + bexcl;
    __syncthreads();
#pragma unroll
    for (int j = 0; j < 16; j++) {
        int idx = base + j * 256 + t;
        if (idx < NK) g_scan[idx] = s_int[j * 256 + t];
    }
    __syncthreads();

    // --- stage km tile (winners; dup rows left stale -> overwritten by k_dup),
    //     collect dup indices ---
    int dcnt = 0;
    int didx[16];
#pragma unroll
    for (int j = 0; j < 16; j++) {
        int l = t * 16 + j;
        int idx = base + l;
        if (idx < NK) {
            int n = idx / K_VOL;
            int k = idx - n * K_VOL;
            if ((fmask >> j) & 1u) {
                int u = v[j] + thr_excl + bexcl - 1;
                s_buf[3 * l]     = (float)n;
                s_buf[3 * l + 1] = (float)u;
                s_buf[3 * l + 2] = (float)k;
            } else {
                didx[dcnt++] = idx;
            }
        }
    }
    __syncthreads();
    {   // coalesced km write: 3*nelem floats, float4 where possible
        float4* dst4 = (float4*)(km + (size_t)3 * base);
        int nf = 3 * nelem;
        int nf4 = nf >> 2;
        for (int q = t; q < nf4; q += 256) dst4[q] = ((float4*)s_buf)[q];
        for (int q = (nf4 << 2) + t; q < nf; q += 256) km[(size_t)3 * base + q] = s_buf[q];
    }
    __syncthreads();

    // --- stage ok tile (winners occupy contiguous u range [bexcl, bexcl+total)) ---
#pragma unroll
    for (int j = 0; j < 16; j++) {
        int l = t * 16 + j;
        int idx = base + l;
        if (idx < NK && ((fmask >> j) & 1u)) {
            int u_loc = v[j] + thr_excl - 1;          // u - bexcl
            int n = idx / K_VOL;
            int k = idx - n * K_VOL;
            s_buf[3 * u_loc]     = (float)(si[N + n]     + (k / 9)       - HALFK);
            s_buf[3 * u_loc + 1] = (float)(si[2 * N + n] + ((k / 3) % 3) - HALFK);
            s_buf[3 * u_loc + 2] = (float)(si[3 * N + n] + (k % 3)       - HALFK);
        }
    }
    __syncthreads();
    {   // coalesced ok write from row bexcl
        float* dst = ok + (size_t)3 * bexcl;
        int nf = 3 * total;
        for (int q = t; q < nf; q += 256) dst[q] = s_buf[q];
    }

    // --- dup compaction (warp-aggregated append) ---
    int inc2 = dcnt;
#pragma unroll
    for (int off = 1; off < 32; off <<= 1) {
        int y = __shfl_up_sync(0xffffffffu, inc2, off);
        if (lane >= off) inc2 += y;
    }
    int wtot = __shfl_sync(0xffffffffu, inc2, 31);
    unsigned db = 0;
    if (lane == 31 && wtot > 0) db = (unsigned)atomicAdd(&g_aux[AUX_DUP], (unsigned long long)wtot);
    db = __shfl_sync(0xffffffffu, db, 31);
    int wbase = (int)db + inc2 - dcnt;
    for (int q = 0; q < dcnt; q++) g_dup[wbase + q] = didx[q];
}

// 3) streaming: winner feature copy + tail zero + tail ok=-1. 8 lanes/row.
__global__ __launch_bounds__(256) void k_featw(int NK, const float4* __restrict__ feat,
                                               float4* __restrict__ outf, float* __restrict__ ok) {
    int tid = blockIdx.x * blockDim.x + threadIdx.x;
    int i = tid >> 3;
    int lane = tid & 7;
    if (i >= NK) return;
    int m = g_slot[i];
    if (m == i) {
        int u = g_scan[i] - 1;
        int n = i / K_VOL;
        outf[(size_t)u * 8 + lane] = feat[(size_t)n * 8 + lane];
    }
    int U = g_scan[NK - 1];
    if (i >= U) {
        outf[(size_t)i * 8 + lane] = make_float4(0.f, 0.f, 0.f, 0.f);
        if (lane == 0) {
            ok[(size_t)3 * i]     = -1.0f;
            ok[(size_t)3 * i + 1] = -1.0f;
            ok[(size_t)3 * i + 2] = -1.0f;
        }
    }
}

// 4) duplicates: km row + atomicAdd features. 4 lanes per dup.
__global__ __launch_bounds__(256) void k_dup(int NK, const float* __restrict__ feat,
                                             float* __restrict__ outf, float* __restrict__ km) {
    int tid = blockIdx.x * blockDim.x + threadIdx.x;
    int j = tid >> 2;
    int lane = tid & 3;
    if (j >= (int)g_aux[AUX_DUP]) return;
    int i = g_dup[j];
    int m = g_slot[i];
    int u = g_scan[m] - 1;
    int n = i / K_VOL;
    int k = i - n * K_VOL;
    if (lane == 0) {
        km[(size_t)3 * i]     = (float)n;
        km[(size_t)3 * i + 1] = (float)u;
        km[(size_t)3 * i + 2] = (float)k;
    }
    const float4* src = (const float4*)(feat + (size_t)n * 32) + lane * 2;
    float4 a = src[0], b = src[1];
    float* dst = outf + (size_t)u * 32 + lane * 8;
    atomicAdd(dst + 0, a.x); atomicAdd(dst + 1, a.y);
    atomicAdd(dst + 2, a.z); atomicAdd(dst + 3, a.w);
    atomicAdd(dst + 4, b.x); atomicAdd(dst + 5, b.y);
    atomicAdd(dst + 6, b.z); atomicAdd(dst + 7, b.w);
}

extern "C" void kernel_launch(void* const* d_in, const int* in_sizes, int n_in,
                              void* d_out, int out_size) {
    const int* si = (const int*)d_in[0];
    const float* feat = (const float*)d_in[1];
    int N = in_sizes[0] / 4;
    int NK = N * K_VOL;

    float* out = (float*)d_out;
    float* out_km = out;
    float* out_ok = out + (size_t)3 * NK;
    float* out_of = out + (size_t)6 * NK;

    static void* p_key = nullptr, *p_val = nullptr, *p_aux = nullptr;
    if (!p_key) {
        cudaGetSymbolAddress(&p_key, g_ht_key);
        cudaGetSymbolAddress(&p_val, g_ht_val);
        cudaGetSymbolAddress(&p_aux, g_aux);
    }

    const int T = 256;
    int gNK = (NK + T - 1) / T;
    int nblk = (NK + SCAN_ELEMS - 1) / SCAN_ELEMS;

    cudaMemsetAsync(p_key, 0xFF, TAB * sizeof(int));                          // -1
    cudaMemsetAsync(p_val, 0x7F, TAB * sizeof(int));                          // 0x7f7f7f7f
    cudaMemsetAsync(p_aux, 0x00, (NBLK_SCAN_MAX + 2) * sizeof(unsigned long long));

    k_build<<<gNK, T>>>(si, N, NK);
    k_scan<<<nblk, T>>>(NK, si, N, out_km, out_ok);
    k_featw<<<(NK * 8 + T - 1) / T, T>>>(NK, (const float4*)feat, (float4*)out_of, out_ok);
    k_dup<<<(NK * 4 + T - 1) / T, T>>>(NK, feat, out_of, out_km);
}

// round 7
// speedup vs baseline: 1.1946x; 1.1856x over previous
#include <cuda_runtime.h>
#include <cstdint>

#define K_VOL 27
#define HALFK 1
#define SENC 258
#define NK_MAX 2700000
#define TAB_BITS 23
#define TAB (1u << TAB_BITS)
#define TMASK (TAB - 1u)
#define SCAN_ELEMS 4096                // 256 threads x 16
#define NBLK_SCAN_MAX 1022

#define AUX_TICKET 0
#define AUX_DUP    1
#define AUX_STATE  2

__device__ int g_ht_key[TAB];          // -1 = empty
__device__ int g_ht_val[TAB];          // min flat index per key (init 0x7f7f7f7f)
__device__ int g_slot[NK_MAX];         // hash slot -> then min flat index
__device__ int g_scan[NK_MAX];         // inclusive scan of winner flags
__device__ int g_dup[NK_MAX];          // compacted duplicate entry indices
__device__ unsigned long long g_aux[NBLK_SCAN_MAX + 2];

// 1) encode + hash insert + atomicMin of flat index
__global__ __launch_bounds__(256) void k_build(const int* __restrict__ si, int N, int NK) {
    int i = blockIdx.x * blockDim.x + threadIdx.x;
    if (i >= NK) return;
    int n = i / K_VOL;
    int k = i - n * K_VOL;
    int b = si[n];
    int x = si[N + n]     + (k / 9);
    int y = si[2 * N + n] + ((k / 3) % 3);
    int z = si[3 * N + n] + (k % 3);
    int enc = ((b * SENC + x) * SENC + y) * SENC + z;

    unsigned h = ((unsigned)enc * 2654435761u) >> (32 - TAB_BITS);
    for (;;) {
        int cur = g_ht_key[h];
        if (cur == enc) break;
        if (cur == -1) {
            cur = atomicCAS(&g_ht_key[h], -1, enc);
            if (cur == -1 || cur == enc) break;
        }
        h = (h + 1) & TMASK;
    }
    atomicMin(&g_ht_val[h], i);
    g_slot[i] = (int)h;
}

// 2) mega-fused: resolve min index, decoupled-lookback scan, km + ok emission,
//    WINNER FEATURE COPY (contiguous dst range per block), dup compaction.
__global__ __launch_bounds__(256) void k_scan(int NK, const int* __restrict__ si, int N,
                                              float* __restrict__ km, float* __restrict__ ok,
                                              const float4* __restrict__ feat,
                                              float4* __restrict__ outf) {
    __shared__ alignas(16) float s_buf[12288];   // 48KB staging
    __shared__ int s_warp[8];
    __shared__ unsigned s_blk;
    __shared__ int s_excl;
    int* s_int = (int*)s_buf;

    int t = threadIdx.x;
    if (t == 0) s_blk = (unsigned)atomicAdd(&g_aux[AUX_TICKET], 1ULL);
    __syncthreads();
    int blk = (int)s_blk;
    int base = blk * SCAN_ELEMS;

    // --- load + resolve min index (coalesced, 16-deep MLP) ---
#pragma unroll
    for (int j = 0; j < 16; j++) {
        int idx = base + j * 256 + t;
        int m = -1;
        if (idx < NK) {
            int s = g_slot[idx];
            m = g_ht_val[s];
            g_slot[idx] = m;
        }
        s_int[j * 256 + t] = m;
    }
    __syncthreads();

    // --- per-thread serial scan over contiguous 16 ---
    int v[16];
    unsigned fmask = 0;
    int run = 0;
#pragma unroll
    for (int j = 0; j < 16; j++) {
        int l = t * 16 + j;
        int f = (s_int[l] == base + l) ? 1 : 0;
        fmask |= (unsigned)f << j;
        run += f;
        v[j] = run;
    }
    __syncthreads();

    // --- warp + block scan of per-thread sums ---
    int lane = t & 31, wid = t >> 5;
    int inc = run;
#pragma unroll
    for (int off = 1; off < 32; off <<= 1) {
        int y = __shfl_up_sync(0xffffffffu, inc, off);
        if (lane >= off) inc += y;
    }
    if (lane == 31) s_warp[wid] = inc;
    __syncthreads();
    if (t < 8) {
        int w = s_warp[t];
#pragma unroll
        for (int off = 1; off < 8; off <<= 1) {
            int y = __shfl_up_sync(0xffu, w, off);
            if ((int)t >= off) w += y;
        }
        s_warp[t] = w;
    }
    __syncthreads();
    int total = s_warp[7];
    int thr_excl = (inc - run) + (wid ? s_warp[wid - 1] : 0);

    // --- decoupled lookback ---
    if (t == 0) {
        unsigned long long* st = &g_aux[AUX_STATE];
        if (blk == 0) {
            atomicExch(&st[0], (2ULL << 32) | (unsigned)total);
            s_excl = 0;
        } else {
            atomicExch(&st[blk], (1ULL << 32) | (unsigned)total);
            int excl = 0;
            int j = blk - 1;
            for (;;) {
                unsigned long long s;
                do { s = atomicAdd(&st[j], 0ULL); } while ((s >> 32) == 0ULL);
                excl += (int)(unsigned)s;
                if ((s >> 32) == 2ULL) break;
                j--;
            }
            atomicExch(&st[blk], (2ULL << 32) | (unsigned)(excl + total));
            s_excl = excl;
        }
    }
    __syncthreads();
    int bexcl = s_excl;
    int nelem = NK - base; if (nelem > SCAN_ELEMS) nelem = SCAN_ELEMS;

    // --- store inclusive scan (coalesced via shared transpose) ---
#pragma unroll
    for (int j = 0; j < 16; j++) s_int[t * 16 + j] = v[j] + thr_excl + bexcl;
    __syncthreads();
#pragma unroll
    for (int j = 0; j < 16; j++) {
        int idx = base + j * 256 + t;
        if (idx < NK) g_scan[idx] = s_int[j * 256 + t];
    }
    __syncthreads();

    // --- stage km tile (winners only; dup rows fixed later by k_dup) + collect dups ---
    int dcnt = 0;
    int didx[16];
#pragma unroll
    for (int j = 0; j < 16; j++) {
        int l = t * 16 + j;
        int idx = base + l;
        if (idx < NK) {
            int n = idx / K_VOL;
            int k = idx - n * K_VOL;
            if ((fmask >> j) & 1u) {
                int u = v[j] + thr_excl + bexcl - 1;
                s_buf[3 * l]     = (float)n;
                s_buf[3 * l + 1] = (float)u;
                s_buf[3 * l + 2] = (float)k;
            } else {
                didx[dcnt++] = idx;
            }
        }
    }
    __syncthreads();
    {   // coalesced km write
        float4* dst4 = (float4*)(km + (size_t)3 * base);
        int nf = 3 * nelem;
        int nf4 = nf >> 2;
        for (int q = t; q < nf4; q += 256) dst4[q] = ((float4*)s_buf)[q];
        for (int q = (nf4 << 2) + t; q < nf; q += 256) km[(size_t)3 * base + q] = s_buf[q];
    }
    __syncthreads();

    // --- stage ok tile (winners occupy contiguous u range [bexcl, bexcl+total)) ---
#pragma unroll
    for (int j = 0; j < 16; j++) {
        int l = t * 16 + j;
        int idx = base + l;
        if (idx < NK && ((fmask >> j) & 1u)) {
            int u_loc = v[j] + thr_excl - 1;
            int n = idx / K_VOL;
            int k = idx - n * K_VOL;
            s_buf[3 * u_loc]     = (float)(si[N + n]     + (k / 9)       - HALFK);
            s_buf[3 * u_loc + 1] = (float)(si[2 * N + n] + ((k / 3) % 3) - HALFK);
            s_buf[3 * u_loc + 2] = (float)(si[3 * N + n] + (k % 3)       - HALFK);
        }
    }
    __syncthreads();
    {   // coalesced ok write from row bexcl
        float* dst = ok + (size_t)3 * bexcl;
        int nf = 3 * total;
        for (int q = t; q < nf; q += 256) dst[q] = s_buf[q];
    }
    __syncthreads();

    // --- stage winner source-row map, then coalesced feature copy ---
#pragma unroll
    for (int j = 0; j < 16; j++) {
        int l = t * 16 + j;
        int idx = base + l;
        if (idx < NK && ((fmask >> j) & 1u)) {
            int u_loc = v[j] + thr_excl - 1;
            s_int[u_loc] = idx / K_VOL;
        }
    }
    __syncthreads();
    {
        float4* dst = outf + (size_t)bexcl * 8;
        int lanes = total * 8;
        for (int q = t; q < lanes; q += 256) {
            int w = q >> 3, ln = q & 7;
            int n = s_int[w];
            dst[(size_t)w * 8 + ln] = feat[(size_t)n * 8 + ln];
        }
    }

    // --- dup compaction (warp-aggregated append) ---
    int inc2 = dcnt;
#pragma unroll
    for (int off = 1; off < 32; off <<= 1) {
        int y = __shfl_up_sync(0xffffffffu, inc2, off);
        if (lane >= off) inc2 += y;
    }
    int wtot = __shfl_sync(0xffffffffu, inc2, 31);
    unsigned db = 0;
    if (lane == 31 && wtot > 0) db = (unsigned)atomicAdd(&g_aux[AUX_DUP], (unsigned long long)wtot);
    db = __shfl_sync(0xffffffffu, db, 31);
    int wbase = (int)db + inc2 - dcnt;
    for (int q = 0; q < dcnt; q++) g_dup[wbase + q] = didx[q];
}

// 3) tail fill [U, NK): persistent grid-stride. 8 lanes/row.
__global__ __launch_bounds__(256) void k_tail(int NK, float4* __restrict__ outf,
                                              float* __restrict__ ok) {
    int U = g_scan[NK - 1];
    long long lanes = (long long)(NK - U) * 8;
    long long stride = (long long)gridDim.x * blockDim.x;
    for (long long q = (long long)blockIdx.x * blockDim.x + threadIdx.x; q < lanes; q += stride) {
        int r = U + (int)(q >> 3);
        int ln = (int)(q & 7);
        outf[(size_t)r * 8 + ln] = make_float4(0.f, 0.f, 0.f, 0.f);
        if (ln == 0) {
            ok[(size_t)3 * r]     = -1.0f;
            ok[(size_t)3 * r + 1] = -1.0f;
            ok[(size_t)3 * r + 2] = -1.0f;
        }
    }
}

// 4) duplicates: persistent grid-stride; km row + atomicAdd features, 4 lanes/dup.
__global__ __launch_bounds__(256) void k_dup(const float* __restrict__ feat,
                                             float* __restrict__ outf,
                                             float* __restrict__ km) {
    int cnt = (int)g_aux[AUX_DUP];
    long long lanes = (long long)cnt * 4;
    long long stride = (long long)gridDim.x * blockDim.x;
    for (long long q = (long long)blockIdx.x * blockDim.x + threadIdx.x; q < lanes; q += stride) {
        int j = (int)(q >> 2);
        int ln = (int)(q & 3);
        int i = g_dup[j];
        int m = g_slot[i];
        int u = g_scan[m] - 1;
        int n = i / K_VOL;
        int k = i - n * K_VOL;
        if (ln == 0) {
            km[(size_t)3 * i]     = (float)n;
            km[(size_t)3 * i + 1] = (float)u;
            km[(size_t)3 * i + 2] = (float)k;
        }
        const float4* src = (const float4*)(feat + (size_t)n * 32) + ln * 2;
        float4 a = src[0], b = src[1];
        float* dst = outf + (size_t)u * 32 + ln * 8;
        atomicAdd(dst + 0, a.x); atomicAdd(dst + 1, a.y);
        atomicAdd(dst + 2, a.z); atomicAdd(dst + 3, a.w);
        atomicAdd(dst + 4, b.x); atomicAdd(dst + 5, b.y);
        atomicAdd(dst + 6, b.z); atomicAdd(dst + 7, b.w);
    }
}

extern "C" void kernel_launch(void* const* d_in, const int* in_sizes, int n_in,
                              void* d_out, int out_size) {
    const int* si = (const int*)d_in[0];
    const float* feat = (const float*)d_in[1];
    int N = in_sizes[0] / 4;
    int NK = N * K_VOL;

    float* out = (float*)d_out;
    float* out_km = out;
    float* out_ok = out + (size_t)3 * NK;
    float* out_of = out + (size_t)6 * NK;

    static void* p_key = nullptr, *p_val = nullptr, *p_aux = nullptr;
    if (!p_key) {
        cudaGetSymbolAddress(&p_key, g_ht_key);
        cudaGetSymbolAddress(&p_val, g_ht_val);
        cudaGetSymbolAddress(&p_aux, g_aux);
    }

    const int T = 256;
    int gNK = (NK + T - 1) / T;
    int nblk = (NK + SCAN_ELEMS - 1) / SCAN_ELEMS;

    cudaMemsetAsync(p_key, 0xFF, TAB * sizeof(int));
    cudaMemsetAsync(p_val, 0x7F, TAB * sizeof(int));
    cudaMemsetAsync(p_aux, 0x00, (NBLK_SCAN_MAX + 2) * sizeof(unsigned long long));

    k_build<<<gNK, T>>>(si, N, NK);
    k_scan<<<nblk, T>>>(NK, si, N, out_km, out_ok, (const float4*)feat, (float4*)out_of);
    k_tail<<<1024, T>>>(NK, (float4*)out_of, out_ok);
    k_dup<<<1024, T>>>(feat, out_of, out_km);
}

// round 8
// speedup vs baseline: 1.2181x; 1.0197x over previous
#include <cuda_runtime.h>
#include <cstdint>

#define K_VOL 27
#define HALFK 1
#define SENC 258
#define NK_MAX 2700000
#define TAB_BITS 23
#define TAB (1u << TAB_BITS)
#define TMASK (TAB - 1u)
#define ENCMASK 0x7FFFFFFULL           // low 27 bits
#define SCAN_ELEMS 4096                // 256 threads x 16
#define NBLK_SCAN_MAX 1022

#define AUX_TICKET 0
#define AUX_DUP    1
#define AUX_STATE  2

__device__ unsigned long long g_ht[TAB];   // packed (min_idx<<27)|enc; ~0 = empty
__device__ int g_slot[NK_MAX];             // hash slot -> then min flat index
__device__ int g_scan[NK_MAX];             // inclusive scan of winner flags
__device__ int2 g_dup[NK_MAX];             // compacted (dup index i, winner index m)
__device__ unsigned long long g_aux[NBLK_SCAN_MAX + 2];

// 1) encode + hash insert: single 64-bit CAS claim, atomicMin for duplicates
__global__ __launch_bounds__(256) void k_build(const int* __restrict__ si, int N, int NK) {
    int i = blockIdx.x * blockDim.x + threadIdx.x;
    if (i >= NK) return;
    int n = i / K_VOL;
    int k = i - n * K_VOL;
    int b = __ldg(si + n);
    int x = __ldg(si + N + n)     + (k / 9);
    int y = __ldg(si + 2 * N + n) + ((k / 3) % 3);
    int z = __ldg(si + 3 * N + n) + (k % 3);
    int enc = ((b * SENC + x) * SENC + y) * SENC + z;

    unsigned long long pack = ((unsigned long long)i << 27) | (unsigned)enc;
    unsigned h = ((unsigned)enc * 2654435761u) >> (32 - TAB_BITS);
    for (;;) {
        unsigned long long cur = g_ht[h];
        if (cur == ~0ULL) {
            cur = atomicCAS(&g_ht[h], ~0ULL, pack);
            if (cur == ~0ULL) break;                       // claimed
        }
        if ((cur & ENCMASK) == (unsigned)enc) {            // same key
            atomicMin(&g_ht[h], pack);
            break;
        }
        h = (h + 1) & TMASK;
    }
    g_slot[i] = (int)h;
}

// 2) mega-fused: resolve min index, decoupled-lookback scan, km + ok emission,
//    winner feature copy (contiguous dst range per block), dup compaction.
__global__ __launch_bounds__(256) void k_scan(int NK, const int* __restrict__ si, int N,
                                              float* __restrict__ km, float* __restrict__ ok,
                                              const float4* __restrict__ feat,
                                              float4* __restrict__ outf) {
    __shared__ alignas(16) float s_buf[12288];   // 48KB staging
    __shared__ int s_warp[8];
    __shared__ unsigned s_blk;
    __shared__ int s_excl;
    int* s_int = (int*)s_buf;

    int t = threadIdx.x;
    if (t == 0) s_blk = (unsigned)atomicAdd(&g_aux[AUX_TICKET], 1ULL);
    __syncthreads();
    int blk = (int)s_blk;
    int base = blk * SCAN_ELEMS;

    // --- load + resolve min index (coalesced, 16-deep MLP) ---
#pragma unroll
    for (int j = 0; j < 16; j++) {
        int idx = base + j * 256 + t;
        int m = -1;
        if (idx < NK) {
            int s = g_slot[idx];
            m = (int)(g_ht[s] >> 27);
            g_slot[idx] = m;
        }
        s_int[j * 256 + t] = m;
    }
    __syncthreads();

    // --- per-thread serial scan over contiguous 16 ---
    int v[16];
    unsigned fmask = 0;
    int run = 0;
#pragma unroll
    for (int j = 0; j < 16; j++) {
        int l = t * 16 + j;
        int f = (s_int[l] == base + l) ? 1 : 0;
        fmask |= (unsigned)f << j;
        run += f;
        v[j] = run;
    }
    __syncthreads();

    // --- warp + block scan of per-thread sums ---
    int lane = t & 31, wid = t >> 5;
    int inc = run;
#pragma unroll
    for (int off = 1; off < 32; off <<= 1) {
        int y = __shfl_up_sync(0xffffffffu, inc, off);
        if (lane >= off) inc += y;
    }
    if (lane == 31) s_warp[wid] = inc;
    __syncthreads();
    if (t < 8) {
        int w = s_warp[t];
#pragma unroll
        for (int off = 1; off < 8; off <<= 1) {
            int y = __shfl_up_sync(0xffu, w, off);
            if ((int)t >= off) w += y;
        }
        s_warp[t] = w;
    }
    __syncthreads();
    int total = s_warp[7];
    int thr_excl = (inc - run) + (wid ? s_warp[wid - 1] : 0);

    // --- decoupled lookback ---
    if (t == 0) {
        unsigned long long* st = &g_aux[AUX_STATE];
        if (blk == 0) {
            atomicExch(&st[0], (2ULL << 32) | (unsigned)total);
            s_excl = 0;
        } else {
            atomicExch(&st[blk], (1ULL << 32) | (unsigned)total);
            int excl = 0;
            int j = blk - 1;
            for (;;) {
                unsigned long long s;
                do { s = atomicAdd(&st[j], 0ULL); } while ((s >> 32) == 0ULL);
                excl += (int)(unsigned)s;
                if ((s >> 32) == 2ULL) break;
                j--;
            }
            atomicExch(&st[blk], (2ULL << 32) | (unsigned)(excl + total));
            s_excl = excl;
        }
    }
    __syncthreads();
    int bexcl = s_excl;
    int nelem = NK - base; if (nelem > SCAN_ELEMS) nelem = SCAN_ELEMS;

    // --- store inclusive scan (coalesced via shared transpose) ---
#pragma unroll
    for (int j = 0; j < 16; j++) s_int[t * 16 + j] = v[j] + thr_excl + bexcl;
    __syncthreads();
#pragma unroll
    for (int j = 0; j < 16; j++) {
        int idx = base + j * 256 + t;
        if (idx < NK) g_scan[idx] = s_int[j * 256 + t];
    }
    __syncthreads();

    // --- stage km tile (winners; dup rows fixed by k_fin) + collect dups ---
    int dcnt = 0;
    int didx[16];
#pragma unroll
    for (int j = 0; j < 16; j++) {
        int l = t * 16 + j;
        int idx = base + l;
        if (idx < NK) {
            int n = idx / K_VOL;
            int k = idx - n * K_VOL;
            if ((fmask >> j) & 1u) {
                int u = v[j] + thr_excl + bexcl - 1;
                s_buf[3 * l]     = (float)n;
                s_buf[3 * l + 1] = (float)u;
                s_buf[3 * l + 2] = (float)k;
            } else {
                didx[dcnt++] = idx;
            }
        }
    }
    __syncthreads();
    {   // coalesced km write
        float4* dst4 = (float4*)(km + (size_t)3 * base);
        int nf = 3 * nelem;
        int nf4 = nf >> 2;
        for (int q = t; q < nf4; q += 256) dst4[q] = ((float4*)s_buf)[q];
        for (int q = (nf4 << 2) + t; q < nf; q += 256) km[(size_t)3 * base + q] = s_buf[q];
    }
    __syncthreads();

    // --- stage ok tile (winners occupy contiguous u range [bexcl, bexcl+total)) ---
#pragma unroll
    for (int j = 0; j < 16; j++) {
        int l = t * 16 + j;
        int idx = base + l;
        if (idx < NK && ((fmask >> j) & 1u)) {
            int u_loc = v[j] + thr_excl - 1;
            int n = idx / K_VOL;
            int k = idx - n * K_VOL;
            s_buf[3 * u_loc]     = (float)(si[N + n]     + (k / 9)       - HALFK);
            s_buf[3 * u_loc + 1] = (float)(si[2 * N + n] + ((k / 3) % 3) - HALFK);
            s_buf[3 * u_loc + 2] = (float)(si[3 * N + n] + (k % 3)       - HALFK);
        }
    }
    __syncthreads();
    {   // coalesced ok write from row bexcl
        float* dst = ok + (size_t)3 * bexcl;
        int nf = 3 * total;
        for (int q = t; q < nf; q += 256) dst[q] = s_buf[q];
    }
    __syncthreads();

    // --- stage winner source-row map, then 4x-batched coalesced feature copy ---
#pragma unroll
    for (int j = 0; j < 16; j++) {
        int l = t * 16 + j;
        int idx = base + l;
        if (idx < NK && ((fmask >> j) & 1u)) {
            int u_loc = v[j] + thr_excl - 1;
            s_int[u_loc] = idx / K_VOL;
        }
    }
    __syncthreads();
    {
        float4* dst = outf + (size_t)bexcl * 8;
        int lanes = total * 8;
        for (int q = t; q < lanes; q += 1024) {
            float4 vals[4];
#pragma unroll
            for (int r = 0; r < 4; r++) {
                int qq = q + r * 256;
                if (qq < lanes) {
                    int w = qq >> 3, ln = qq & 7;
                    int n = s_int[w];
                    vals[r] = feat[(size_t)n * 8 + ln];
                }
            }
#pragma unroll
            for (int r = 0; r < 4; r++) {
                int qq = q + r * 256;
                if (qq < lanes) dst[qq] = vals[r];
            }
        }
    }

    // --- dup compaction (warp-aggregated append, store (i, m)) ---
    int inc2 = dcnt;
#pragma unroll
    for (int off = 1; off < 32; off <<= 1) {
        int y = __shfl_up_sync(0xffffffffu, inc2, off);
        if (lane >= off) inc2 += y;
    }
    int wtot = __shfl_sync(0xffffffffu, inc2, 31);
    unsigned db = 0;
    if (lane == 31 && wtot > 0) db = (unsigned)atomicAdd(&g_aux[AUX_DUP], (unsigned long long)wtot);
    db = __shfl_sync(0xffffffffu, db, 31);
    int wbase = (int)db + inc2 - dcnt;
    for (int q = 0; q < dcnt; q++) {
        int i = didx[q];
        g_dup[wbase + q] = make_int2(i, g_slot[i]);   // g_slot[i] = m (L2-hot)
    }
}

// 3) fused finale: dup km rows + feature atomicAdds, AND tail fill [U, NK).
__global__ __launch_bounds__(256) void k_fin(int NK, const float* __restrict__ feat,
                                             float* __restrict__ outf, float* __restrict__ km,
                                             float4* __restrict__ outf4, float* __restrict__ ok) {
    long long stride = (long long)gridDim.x * blockDim.x;
    long long tid0 = (long long)blockIdx.x * blockDim.x + threadIdx.x;

    // dups: 4 lanes per dup
    int cnt = (int)g_aux[AUX_DUP];
    long long dlanes = (long long)cnt * 4;
    for (long long q = tid0; q < dlanes; q += stride) {
        int j = (int)(q >> 2);
        int ln = (int)(q & 3);
        int2 im = g_dup[j];
        int i = im.x, m = im.y;
        int u = g_scan[m] - 1;
        int n = i / K_VOL;
        int k = i - n * K_VOL;
        if (ln == 0) {
            km[(size_t)3 * i]     = (float)n;
            km[(size_t)3 * i + 1] = (float)u;
            km[(size_t)3 * i + 2] = (float)k;
        }
        const float4* src = (const float4*)(feat + (size_t)n * 32) + ln * 2;
        float4 a = src[0], b = src[1];
        float* dst = outf + (size_t)u * 32 + ln * 8;
        atomicAdd(dst + 0, a.x); atomicAdd(dst + 1, a.y);
        atomicAdd(dst + 2, a.z); atomicAdd(dst + 3, a.w);
        atomicAdd(dst + 4, b.x); atomicAdd(dst + 5, b.y);
        atomicAdd(dst + 6, b.z); atomicAdd(dst + 7, b.w);
    }

    // tail: 8 lanes per row
    int U = g_scan[NK - 1];
    long long tlanes = (long long)(NK - U) * 8;
    for (long long q = tid0; q < tlanes; q += stride) {
        int r = U + (int)(q >> 3);
        int ln = (int)(q & 7);
        outf4[(size_t)r * 8 + ln] = make_float4(0.f, 0.f, 0.f, 0.f);
        if (ln == 0) {
            ok[(size_t)3 * r]     = -1.0f;
            ok[(size_t)3 * r + 1] = -1.0f;
            ok[(size_t)3 * r + 2] = -1.0f;
        }
    }
}

extern "C" void kernel_launch(void* const* d_in, const int* in_sizes, int n_in,
                              void* d_out, int out_size) {
    const int* si = (const int*)d_in[0];
    const float* feat = (const float*)d_in[1];
    int N = in_sizes[0] / 4;
    int NK = N * K_VOL;

    float* out = (float*)d_out;
    float* out_km = out;
    float* out_ok = out + (size_t)3 * NK;
    float* out_of = out + (size_t)6 * NK;

    static void* p_ht = nullptr, *p_aux = nullptr;
    if (!p_ht) {
        cudaGetSymbolAddress(&p_ht, g_ht);
        cudaGetSymbolAddress(&p_aux, g_aux);
    }

    const int T = 256;
    int gNK = (NK + T - 1) / T;
    int nblk = (NK + SCAN_ELEMS - 1) / SCAN_ELEMS;

    cudaMemsetAsync(p_ht, 0xFF, TAB * sizeof(unsigned long long));
    cudaMemsetAsync(p_aux, 0x00, (NBLK_SCAN_MAX + 2) * sizeof(unsigned long long));

    k_build<<<gNK, T>>>(si, N, NK);
    k_scan<<<nblk, T>>>(NK, si, N, out_km, out_ok, (const float4*)feat, (float4*)out_of);
    k_fin<<<1024, T>>>(NK, feat, out_of, out_km, (float4*)out_of, out_ok);
}